// round 4
// baseline (speedup 1.0000x reference)
#include <cuda_runtime.h>
#include <math.h>

#define D 512
#define NBLOCKS 1184
#define BLK 256
#define WARPS_PER_BLK (BLK / 32)
#define EPSN (1e-13f + 1e-14f)

__device__ float g_partial[NBLOCKS];
__device__ unsigned int g_count;  // zero-initialized; last block wraps it back to 0

__device__ __forceinline__ float warp_reduce_add(float v) {
#pragma unroll
    for (int off = 16; off > 0; off >>= 1)
        v += __shfl_xor_sync(0xffffffffu, v, off);
    return v;
}

__global__ __launch_bounds__(BLK) void rowcos_fused_kernel(const float* __restrict__ s,
                                                           const float* __restrict__ im,
                                                           float* __restrict__ out,
                                                           int N) {
    const int lane = threadIdx.x & 31;
    const int gwarp = (blockIdx.x * BLK + threadIdx.x) >> 5;
    const int nwarps = (gridDim.x * BLK) >> 5;

    float acc = 0.0f;

    for (int row = gwarp; row < N; row += nwarps) {
        const float4* sp = reinterpret_cast<const float4*>(s + (size_t)row * D);
        const float4* ip = reinterpret_cast<const float4*>(im + (size_t)row * D);

        // 128 float4 per row per array; 32 lanes -> 4 float4 each. 8 independent
        // loads in flight per lane (MLP=8) hides DRAM latency.
        float4 a[4], b[4];
#pragma unroll
        for (int j = 0; j < 4; j++) {
            a[j] = sp[lane + j * 32];
            b[j] = ip[lane + j * 32];
        }

        float dot = 0.0f, ss = 0.0f, ii = 0.0f;
#pragma unroll
        for (int j = 0; j < 4; j++) {
            dot += a[j].x * b[j].x + a[j].y * b[j].y + a[j].z * b[j].z + a[j].w * b[j].w;
            ss  += a[j].x * a[j].x + a[j].y * a[j].y + a[j].z * a[j].z + a[j].w * a[j].w;
            ii  += b[j].x * b[j].x + b[j].y * b[j].y + b[j].z * b[j].z + b[j].w * b[j].w;
        }

        dot = warp_reduce_add(dot);
        ss  = warp_reduce_add(ss);
        ii  = warp_reduce_add(ii);

        if (lane == 0) {
            acc -= dot / ((sqrtf(ss) + EPSN) * (sqrtf(ii) + EPSN));
        }
    }

    __shared__ float wsum[WARPS_PER_BLK];
    if (lane == 0) wsum[threadIdx.x >> 5] = acc;
    __syncthreads();

    __shared__ bool is_last;
    if (threadIdx.x == 0) {
        float bsum = 0.0f;
#pragma unroll
        for (int w = 0; w < WARPS_PER_BLK; w++) bsum += wsum[w];
        g_partial[blockIdx.x] = bsum;
        __threadfence();
        unsigned int done = atomicInc(&g_count, NBLOCKS - 1);  // wraps to 0 at last block
        is_last = (done == NBLOCKS - 1);
    }
    __syncthreads();

    if (is_last) {
        // Deterministic final sum: fixed-order strided accumulate + shared tree.
        __shared__ float sm[BLK];
        float v = 0.0f;
        for (int i = threadIdx.x; i < NBLOCKS; i += BLK) v += g_partial[i];
        sm[threadIdx.x] = v;
        __syncthreads();
#pragma unroll
        for (int step = BLK / 2; step > 0; step >>= 1) {
            if (threadIdx.x < step) sm[threadIdx.x] += sm[threadIdx.x + step];
            __syncthreads();
        }
        if (threadIdx.x == 0) out[0] = sm[0];
    }
}

extern "C" void kernel_launch(void* const* d_in, const int* in_sizes, int n_in,
                              void* d_out, int out_size) {
    const float* s  = (const float*)d_in[0];
    const float* im = (const float*)d_in[1];
    const int N = in_sizes[0] / D;

    rowcos_fused_kernel<<<NBLOCKS, BLK>>>(s, im, (float*)d_out, N);
}